// round 2
// baseline (speedup 1.0000x reference)
#include <cuda_runtime.h>
#include <cstdint>
#include <cstddef>

#define S_DIM 8
#define U_DIM 8
#define SU    64
#define NK    12
#define NEG   17
#define ZD    64
#define CD    256
#define T_DIM 1140
#define LEN   1128
#define SCALE 0.125f

// Scratch: Wc[su][l][z] for ONE k at a time (64*1128*64 floats = ~18.5 MB).
// Stream order serializes gemm(k) -> score(k) -> gemm(k+1), so reuse is safe
// and keeps the tile L2-resident for the score pass.
__device__ float  g_Wc[(size_t)SU * LEN * ZD];
__device__ double g_loss[NK];
__device__ int    g_acc[NK];

// ---------------------------------------------------------------------------
// Kernel 1: Wc[su][l][z] = sum_d c[su][l][d] * W[k][z][d] + b[k][z]
// Tiled fp32 GEMM. Block = 256 threads, tile 128(l) x 64(z), BK=16.
// Both operand tiles stored d-major (transposed) in smem so the inner loop is
// float4 loads: a = 8 m-values, b = 4 z-values. Per d: 3 LDS.128 + 32 FFMA.
// ---------------------------------------------------------------------------
#define BM 128
#define BK 16

__global__ __launch_bounds__(256) void gemm_wc(
    const float* __restrict__ c, const float* __restrict__ W,
    const float* __restrict__ bias, const int kk)
{
    __shared__ __align__(16) float cs[BK][BM + 4];   // [d][m]
    __shared__ __align__(16) float ws[BK][ZD + 4];   // [d][z]

    const int su = blockIdx.y;
    const int l0 = blockIdx.x * BM;
    const int tid = threadIdx.x;
    const int tm = tid >> 4;      // 0..15  -> rows m0 = tm*8
    const int tn = tid & 15;      // 0..15  -> cols n0 = tn*4

    float acc[8][4];
    #pragma unroll
    for (int i = 0; i < 8; i++)
        #pragma unroll
        for (int j = 0; j < 4; j++) acc[i][j] = 0.f;

    const float* cb = c + (size_t)su * T_DIM * CD;
    const float* wb = W + (size_t)kk * ZD * CD;

    for (int d0 = 0; d0 < CD; d0 += BK) {
        // load + transpose c tile: 128 rows x 16 d  (2 float4 per thread)
        #pragma unroll
        for (int i = 0; i < 2; i++) {
            int idx = tid + i * 256;
            int m   = idx >> 2;
            int dq  = (idx & 3) * 4;
            float4 v = make_float4(0.f, 0.f, 0.f, 0.f);
            int l = l0 + m;
            if (l < LEN) v = *(const float4*)(cb + (size_t)l * CD + d0 + dq);
            cs[dq + 0][m] = v.x; cs[dq + 1][m] = v.y;
            cs[dq + 2][m] = v.z; cs[dq + 3][m] = v.w;
        }
        // load + transpose W tile: 64 z x 16 d  (1 float4 per thread)
        {
            int zr = tid >> 2;
            int dq = (tid & 3) * 4;
            float4 v = *(const float4*)(wb + (size_t)zr * CD + d0 + dq);
            ws[dq + 0][zr] = v.x; ws[dq + 1][zr] = v.y;
            ws[dq + 2][zr] = v.z; ws[dq + 3][zr] = v.w;
        }
        __syncthreads();

        #pragma unroll
        for (int d = 0; d < BK; d++) {
            float4 a0 = *(const float4*)&cs[d][tm * 8];
            float4 a1 = *(const float4*)&cs[d][tm * 8 + 4];
            float4 b  = *(const float4*)&ws[d][tn * 4];
            float am[8] = {a0.x, a0.y, a0.z, a0.w, a1.x, a1.y, a1.z, a1.w};
            float bn[4] = {b.x, b.y, b.z, b.w};
            #pragma unroll
            for (int i = 0; i < 8; i++)
                #pragma unroll
                for (int j = 0; j < 4; j++)
                    acc[i][j] = fmaf(am[i], bn[j], acc[i][j]);
        }
        __syncthreads();
    }

    float4 bv = *(const float4*)(bias + kk * ZD + tn * 4);
    float* out = g_Wc + (size_t)su * LEN * ZD;
    #pragma unroll
    for (int i = 0; i < 8; i++) {
        int l = l0 + tm * 8 + i;
        if (l < LEN) {
            float4 v = make_float4(acc[i][0] + bv.x, acc[i][1] + bv.y,
                                   acc[i][2] + bv.z, acc[i][3] + bv.w);
            *(float4*)(out + (size_t)l * ZD + tn * 4) = v;
        }
    }
}

// ---------------------------------------------------------------------------
// Kernel 2: scoring for step k. One warp per l (3 l's per warp), 8 warps/blk.
// Per l: 18 dots of dim 64 (lane holds 2 dims via float2), butterfly-reduce
// all 18 partials together, then logsumexp + argmax redundantly on all lanes.
// Accumulate per-k loss (double atomic) and acc count (int atomic).
// ---------------------------------------------------------------------------
__global__ __launch_bounds__(256) void score_kernel(
    const float* __restrict__ z, const int* __restrict__ bidx,
    const int* __restrict__ sidx, const int kk)
{
    const int su = blockIdx.y;
    const int s = su >> 3, u = su & 7;

    __shared__ int sbi[NEG];
    const int tid = threadIdx.x;
    if (tid < NEG) sbi[tid] = bidx[(kk * U_DIM + u) * NEG + tid];
    __syncthreads();

    const int warp = tid >> 5, lane = tid & 31;
    const float* wcb = g_Wc + (size_t)su * LEN * ZD;
    const int*   sib = sidx + ((((size_t)kk * S_DIM + s) * U_DIM + u) * NEG) * LEN;
    const float* zsp = z + (size_t)(s * U_DIM) * T_DIM * ZD;   // speaker base

    float loss_local = 0.f;
    int   acc_local  = 0;

    #pragma unroll
    for (int li = 0; li < 3; li++) {
        const int l = blockIdx.x * 24 + warp * 3 + li;  // 47*24 = 1128, exact

        const float2 wc = *(const float2*)(wcb + (size_t)l * ZD + lane * 2);
        float f[NEG + 1];

        {   // positive: z_shift[s,u,l] = z[su, l+k]
            const float2 zs = *(const float2*)(
                z + ((size_t)su * T_DIM + (l + kk + 1)) * ZD + lane * 2);
            f[0] = zs.x * wc.x + zs.y * wc.y;
        }
        #pragma unroll
        for (int n = 0; n < NEG; n++) {
            const int si = sib[(size_t)n * LEN + l];   // uniform across warp
            const int bi = sbi[n];
            const float2 zn = *(const float2*)(
                zsp + ((size_t)bi * T_DIM + (si + kk + 1)) * ZD + lane * 2);
            f[1 + n] = zn.x * wc.x + zn.y * wc.y;
        }

        // butterfly reduce all 18 dot partials across the warp
        #pragma unroll
        for (int off = 16; off; off >>= 1)
            #pragma unroll
            for (int i = 0; i < NEG + 1; i++)
                f[i] += __shfl_xor_sync(0xffffffffu, f[i], off);

        // scale, argmax (first max), logsumexp — redundantly on all lanes
        f[0] *= SCALE;
        float m = f[0]; int am = 0;
        #pragma unroll
        for (int i = 1; i < NEG + 1; i++) {
            f[i] *= SCALE;
            if (f[i] > m) { m = f[i]; am = i; }
        }
        float ssum = 0.f;
        #pragma unroll
        for (int i = 0; i < NEG + 1; i++) ssum += __expf(f[i] - m);
        loss_local += (m + __logf(ssum)) - f[0];
        acc_local  += (am == 0) ? 1 : 0;
    }

    if (lane == 0) {
        atomicAdd(&g_loss[kk], (double)loss_local);
        atomicAdd(&g_acc[kk], acc_local);
    }
}

// ---------------------------------------------------------------------------
// Kernel 0/3: zero accumulators, finalize output.
// d_out layout: [loss, acc_0 .. acc_11]  (13 floats)
// ---------------------------------------------------------------------------
__global__ void zero_kernel()
{
    int t = threadIdx.x;
    if (t < NK) { g_loss[t] = 0.0; g_acc[t] = 0; }
}

__global__ void final_kernel(float* __restrict__ out)
{
    int t = threadIdx.x;
    if (t < NK)
        out[1 + t] = (float)((double)g_acc[t] / (double)(SU * LEN));
    if (t == 0) {
        double tot = 0.0;
        for (int i = 0; i < NK; i++) tot += g_loss[i];   // fixed order
        out[0] = (float)(tot / ((double)NK * SU * LEN));
    }
}

// ---------------------------------------------------------------------------
extern "C" void kernel_launch(void* const* d_in, const int* in_sizes, int n_in,
                              void* d_out, int out_size)
{
    const float* z    = (const float*)d_in[0];
    const float* c    = (const float*)d_in[1];
    const float* W    = (const float*)d_in[2];
    const float* b    = (const float*)d_in[3];
    const int*   bidx = (const int*)d_in[4];
    const int*   sidx = (const int*)d_in[5];
    float* out = (float*)d_out;

    zero_kernel<<<1, 32>>>();
    for (int kk = 0; kk < NK; kk++) {
        gemm_wc<<<dim3(9, SU), 256>>>(c, W, b, kk);
        score_kernel<<<dim3(47, SU), 256>>>(z, bidx, sidx, kk);
    }
    final_kernel<<<1, 32>>>(out);
}

// round 3
// speedup vs baseline: 1.6977x; 1.6977x over previous
#include <cuda_runtime.h>
#include <cstdint>
#include <cstddef>

#define S_DIM 8
#define U_DIM 8
#define SU    64
#define NK    12
#define NEG   17
#define ZD    64
#define CD    256
#define T_DIM 1140
#define LEN   1128
#define SCALE 0.125f

// Scratch: Wc[su][l][z] for ONE k at a time (~18.5 MB, L2-resident for score).
__device__ float  g_Wc[(size_t)SU * LEN * ZD];
__device__ double g_loss[NK];
__device__ int    g_acc[NK];

// ---------------------------------------------------------------------------
// Packed fp32x2 FMA (Blackwell): acc = a * b + acc on two lanes of a 64-bit reg.
// Exact fp32 semantics, halves the issue slots of the GEMM mainloop.
// ---------------------------------------------------------------------------
__device__ __forceinline__ void ffma2(unsigned long long& acc,
                                      unsigned long long a,
                                      unsigned long long b)
{
    asm("fma.rn.f32x2 %0, %1, %2, %3;" : "=l"(acc) : "l"(a), "l"(b), "l"(acc));
}
__device__ __forceinline__ unsigned long long splat2(float v)
{
    unsigned long long r;
    asm("mov.b64 %0, {%1, %1};" : "=l"(r) : "f"(v));
    return r;
}
__device__ __forceinline__ void unpack2(unsigned long long v, float& lo, float& hi)
{
    asm("mov.b64 {%0, %1}, %2;" : "=f"(lo), "=f"(hi) : "l"(v));
}

// ---------------------------------------------------------------------------
// Kernel 1: Wc[su][l][z] = sum_d c[su][l][d] * W[k][z][d] + b[k][z]
// Tile 128(l) x 64(z), BK=16, 256 threads; mainloop uses FFMA2:
// per d: 3 LDS.128 + 8 MOV(splat) + 16 FFMA2  ->  fma-pipe bound.
// ---------------------------------------------------------------------------
#define BM 128
#define BK 16

__global__ __launch_bounds__(256) void gemm_wc(
    const float* __restrict__ c, const float* __restrict__ W,
    const float* __restrict__ bias, const int kk)
{
    __shared__ __align__(16) float cs[BK][BM + 4];   // [d][m]
    __shared__ __align__(16) float ws[BK][ZD + 4];   // [d][z]

    const int su = blockIdx.y;
    const int l0 = blockIdx.x * BM;
    const int tid = threadIdx.x;
    const int tm = tid >> 4;      // 0..15  -> rows m0 = tm*8
    const int tn = tid & 15;      // 0..15  -> cols n0 = tn*4

    // accp[p][j]: packed pair of rows (2p, 2p+1) for column j
    unsigned long long accp[4][4];
    #pragma unroll
    for (int p = 0; p < 4; p++)
        #pragma unroll
        for (int j = 0; j < 4; j++) accp[p][j] = 0ull;

    const float* cb = c + (size_t)su * T_DIM * CD;
    const float* wb = W + (size_t)kk * ZD * CD;

    for (int d0 = 0; d0 < CD; d0 += BK) {
        // load + transpose c tile: 128 rows x 16 d  (2 float4 per thread)
        #pragma unroll
        for (int i = 0; i < 2; i++) {
            int idx = tid + i * 256;
            int m   = idx >> 2;
            int dq  = (idx & 3) * 4;
            float4 v = make_float4(0.f, 0.f, 0.f, 0.f);
            int l = l0 + m;
            if (l < LEN) v = *(const float4*)(cb + (size_t)l * CD + d0 + dq);
            cs[dq + 0][m] = v.x; cs[dq + 1][m] = v.y;
            cs[dq + 2][m] = v.z; cs[dq + 3][m] = v.w;
        }
        // load + transpose W tile: 64 z x 16 d  (1 float4 per thread)
        {
            int zr = tid >> 2;
            int dq = (tid & 3) * 4;
            float4 v = *(const float4*)(wb + (size_t)zr * CD + d0 + dq);
            ws[dq + 0][zr] = v.x; ws[dq + 1][zr] = v.y;
            ws[dq + 2][zr] = v.z; ws[dq + 3][zr] = v.w;
        }
        __syncthreads();

        #pragma unroll
        for (int d = 0; d < BK; d++) {
            // a: 8 consecutive m-values as 4 packed pairs (free reinterpret of LDS.128)
            ulonglong2 a01 = *(const ulonglong2*)&cs[d][tm * 8];
            ulonglong2 a23 = *(const ulonglong2*)&cs[d][tm * 8 + 4];
            unsigned long long ap[4] = {a01.x, a01.y, a23.x, a23.y};
            float4 b = *(const float4*)&ws[d][tn * 4];
            unsigned long long bs[4] = {splat2(b.x), splat2(b.y),
                                        splat2(b.z), splat2(b.w)};
            #pragma unroll
            for (int p = 0; p < 4; p++)
                #pragma unroll
                for (int j = 0; j < 4; j++)
                    ffma2(accp[p][j], ap[p], bs[j]);
        }
        __syncthreads();
    }

    float4 bv = *(const float4*)(bias + kk * ZD + tn * 4);
    const float bvf[4] = {bv.x, bv.y, bv.z, bv.w};
    float* out = g_Wc + (size_t)su * LEN * ZD;
    #pragma unroll
    for (int p = 0; p < 4; p++) {
        float r0[4], r1[4];
        #pragma unroll
        for (int j = 0; j < 4; j++) {
            unpack2(accp[p][j], r0[j], r1[j]);
            r0[j] += bvf[j]; r1[j] += bvf[j];
        }
        int lA = l0 + tm * 8 + 2 * p;
        if (lA < LEN)
            *(float4*)(out + (size_t)lA * ZD + tn * 4) =
                make_float4(r0[0], r0[1], r0[2], r0[3]);
        if (lA + 1 < LEN)
            *(float4*)(out + (size_t)(lA + 1) * ZD + tn * 4) =
                make_float4(r1[0], r1[1], r1[2], r1[3]);
    }
}

// ---------------------------------------------------------------------------
// Kernel 2: scoring for step k.
// 8-lane groups: each group owns one l; lane owns 8 of the 64 dims (2 float4).
// Warp = 4 groups = 4 l's processed simultaneously -> reduce/epilogue
// warp-instructions amortized 4x; octet butterfly is 3 levels (not 5).
// Grid (12, 64): group g handles l = g + 384*i, i<3 (384*3=1152 >= 1128).
// All lanes always execute (l clamped, contributions masked) so full-mask
// shfl is safe.
// ---------------------------------------------------------------------------
__global__ __launch_bounds__(256) void score_kernel(
    const float* __restrict__ z, const int* __restrict__ bidx,
    const int* __restrict__ sidx, const int kk)
{
    const int su = blockIdx.y;
    const int s = su >> 3, u = su & 7;
    const int tid = threadIdx.x;

    __shared__ int sbi[NEG];
    __shared__ float blk_loss;
    __shared__ int   blk_acc;
    if (tid < NEG) sbi[tid] = bidx[(kk * U_DIM + u) * NEG + tid];
    if (tid == 0) { blk_loss = 0.f; blk_acc = 0; }
    __syncthreads();

    const int warp = tid >> 5, lane = tid & 31;
    const int grp = lane >> 3, lg = lane & 7;
    const int gg = (blockIdx.x * 8 + warp) * 4 + grp;   // 0..383
    const int d0 = lg * 8;

    const float* wcb = g_Wc + (size_t)su * LEN * ZD;
    const int*   sib = sidx + ((((size_t)kk * S_DIM + s) * U_DIM + u) * NEG) * LEN;
    const float* zsp = z + (size_t)(s * U_DIM) * T_DIM * ZD;   // speaker base

    float loss_local = 0.f;
    int   acc_local  = 0;

    #pragma unroll
    for (int it = 0; it < 3; it++) {
        const int l = gg + 384 * it;
        const bool valid = (l < LEN);
        const int lx = valid ? l : 0;

        const float4 wa = *(const float4*)(wcb + (size_t)lx * ZD + d0);
        const float4 wb = *(const float4*)(wcb + (size_t)lx * ZD + d0 + 4);

        float f[NEG + 1];
        {   // positive: z[su, l+k]
            const float* zr = z + ((size_t)su * T_DIM + (lx + kk + 1)) * ZD + d0;
            const float4 p0 = *(const float4*)zr;
            const float4 p1 = *(const float4*)(zr + 4);
            f[0] = p0.x * wa.x + p0.y * wa.y + p0.z * wa.z + p0.w * wa.w
                 + p1.x * wb.x + p1.y * wb.y + p1.z * wb.z + p1.w * wb.w;
        }
        #pragma unroll
        for (int n = 0; n < NEG; n++) {
            const int si = sib[(size_t)n * LEN + lx];
            const int bi = sbi[n];
            const float* zr = zsp + ((size_t)bi * T_DIM + (si + kk + 1)) * ZD + d0;
            const float4 p0 = *(const float4*)zr;
            const float4 p1 = *(const float4*)(zr + 4);
            f[1 + n] = p0.x * wa.x + p0.y * wa.y + p0.z * wa.z + p0.w * wa.w
                     + p1.x * wb.x + p1.y * wb.y + p1.z * wb.z + p1.w * wb.w;
        }

        // octet butterfly (3 levels), stays within the 8-lane group
        #pragma unroll
        for (int off = 4; off; off >>= 1)
            #pragma unroll
            for (int i = 0; i < NEG + 1; i++)
                f[i] += __shfl_xor_sync(0xffffffffu, f[i], off);

        // epilogue (redundant across the 8 group lanes; warp covers 4 l's)
        f[0] *= SCALE;
        float m = f[0]; int am = 0;
        #pragma unroll
        for (int i = 1; i < NEG + 1; i++) {
            f[i] *= SCALE;
            if (f[i] > m) { m = f[i]; am = i; }
        }
        float ssum = 0.f;
        #pragma unroll
        for (int i = 0; i < NEG + 1; i++) ssum += __expf(f[i] - m);

        if (valid) {
            loss_local += (m + __logf(ssum)) - f[0];
            acc_local  += (am == 0) ? 1 : 0;
        }
    }

    // deduplicate (group lanes hold identical values) + block reduction
    float lval = (lg == 0) ? loss_local : 0.f;
    int   aval = (lg == 0) ? acc_local  : 0;
    lval += __shfl_xor_sync(0xffffffffu, lval, 8);
    lval += __shfl_xor_sync(0xffffffffu, lval, 16);
    aval += __shfl_xor_sync(0xffffffffu, aval, 8);
    aval += __shfl_xor_sync(0xffffffffu, aval, 16);
    if (lane == 0) {
        atomicAdd(&blk_loss, lval);
        atomicAdd(&blk_acc, aval);
    }
    __syncthreads();
    if (tid == 0) {
        atomicAdd(&g_loss[kk], (double)blk_loss);
        atomicAdd(&g_acc[kk], blk_acc);
    }
}

// ---------------------------------------------------------------------------
// Kernel 0/3: zero accumulators, finalize output.
// d_out layout: [loss, acc_0 .. acc_11]
// ---------------------------------------------------------------------------
__global__ void zero_kernel()
{
    int t = threadIdx.x;
    if (t < NK) { g_loss[t] = 0.0; g_acc[t] = 0; }
}

__global__ void final_kernel(float* __restrict__ out)
{
    int t = threadIdx.x;
    if (t < NK)
        out[1 + t] = (float)((double)g_acc[t] / (double)(SU * LEN));
    if (t == 0) {
        double tot = 0.0;
        for (int i = 0; i < NK; i++) tot += g_loss[i];   // fixed order
        out[0] = (float)(tot / ((double)NK * SU * LEN));
    }
}

// ---------------------------------------------------------------------------
extern "C" void kernel_launch(void* const* d_in, const int* in_sizes, int n_in,
                              void* d_out, int out_size)
{
    const float* z    = (const float*)d_in[0];
    const float* c    = (const float*)d_in[1];
    const float* W    = (const float*)d_in[2];
    const float* b    = (const float*)d_in[3];
    const int*   bidx = (const int*)d_in[4];
    const int*   sidx = (const int*)d_in[5];
    float* out = (float*)d_out;

    zero_kernel<<<1, 32>>>();
    for (int kk = 0; kk < NK; kk++) {
        gemm_wc<<<dim3(9, SU), 256>>>(c, W, b, kk);
        score_kernel<<<dim3(12, SU), 256>>>(z, bidx, sidx, kk);
    }
    final_kernel<<<1, 32>>>(out);
}